// round 15
// baseline (speedup 1.0000x reference)
#include <cuda_runtime.h>
#include <cuda_bf16.h>
#include <math.h>
#include <stdint.h>

#define NPTS 4096
#define FIN  6
#define C1   1000
#define C2   1000
#define KNN  40
#define NRB  20
#define SCC_S 205
#define NCLS 40
#define KCAT 6000          // 6 * C1 concatenated Chebyshev basis
#define KSEG1 1024         // padded K, adjacency (1000 -> 1024)
#define KSEG2 6016         // padded K, conv2 (6000 -> 6016)
#define NPAD2 1024         // padded N for conv2 B operand
#define KREEB 3000         // concatenated Reeb basis [vfr|Tr1|Tr2]

// ---------------- scratch (device globals; no allocation) ----------------
__device__ float g_A[(size_t)NPTS * NPTS];       // adjacency scores s = -d^2
__device__ float g_out [(size_t)NPTS * C1];
__device__ float g_out2[(size_t)NPTS * C2];
__device__ float g_TxA [(size_t)NPTS * C1];      // Chebyshev fp32 ping
__device__ float g_TxB [(size_t)NPTS * C1];      // Chebyshev fp32 pong
__device__ float g_xhat1[(size_t)NPTS * 18];
__device__ float g_M1[NPTS * FIN];
__device__ float g_M2[NPTS * FIN];
__device__ float g_T2v[NPTS * FIN];
__device__ float g_sq [NPTS];
__device__ float g_sq2[NPTS];
__device__ float g_dinv[NPTS];
__device__ int   g_kidx[NPTS * KNN];
__device__ float g_kval[NPTS * KNN];
__device__ float g_rcat[NRB * KREEB];            // [vfr | Tr1 | Tr2] concatenated
__device__ float g_outr[NRB * C1];
__device__ float g_feat[2 * C2];
__device__ float g_h1[512];
__device__ float g_h2[128];
__device__ float g_ss[2];
__device__ float g_cmpart[32 * C2];
__device__ float g_regpart[16 * C1 * 6];
// bf16 hi/lo packed operands: row-major [rows, 2*Kseg] (hi at k, lo at Kseg+k)
__device__ __align__(16) unsigned short g_packA1[(size_t)NPTS * 2 * KSEG1];   // out split
__device__ __align__(16) unsigned short g_packA2[(size_t)NPTS * 2 * KSEG2];   // xhat2 split
__device__ __align__(16) unsigned short g_packB2[(size_t)NPAD2 * 2 * KSEG2];  // W2^T split

// ================= helpers =================
__device__ __forceinline__ uint32_t smem_u32(const void* p) {
    uint32_t a;
    asm("{ .reg .u64 t; cvta.to.shared.u64 t, %1; cvt.u32.u64 %0, t; }" : "=r"(a) : "l"(p));
    return a;
}
__device__ __forceinline__ void split_bf16(float v, unsigned short& h, unsigned short& l) {
    __nv_bfloat16 hb = __float2bfloat16(v);
    float lo = v - __bfloat162float(hb);
    __nv_bfloat16 lb = __float2bfloat16(lo);
    h = *(unsigned short*)&hb;
    l = *(unsigned short*)&lb;
}

// ============ tensor-core GEMM: C = A2 @ B2^T via bf16 hi/lo 3-pass ============
// A packed [M, 2*Kseg], B packed [Npad, 2*Kseg]. Segment schedule A{h,h,l}, B{h,l,h}.
// MODE 4: C = 2*acc - aux[gm] - aux[gn]  (= -d^2; exp deferred to topk)
//         SYM=1: only tiles intersecting upper triangle; direct store iff gm<=gn,
//                mirror store iff gm<gn (exactly one writer per element).
// MODE 2: C = relu(acc + aux[gn]) for gn < Nreal    (bias + relu)
// Tile 128(M)x256(N)x32(K); 8 warps of 64x64 (2 in m, 4 in n); 2-stage cp.async.
// smem: 2*(8KB A + 16KB B) = 48KB static. XOR swizzle (group g at g ^ (row&3)).
template<int MODE, int SYM>
__global__ void __launch_bounds__(256)
gemm_mma(const unsigned short* __restrict__ Ap, int ldA,
         const unsigned short* __restrict__ Bp, int ldB,
         int Kseg, int Nreal, float* __restrict__ C, int ldc,
         const float* __restrict__ aux) {
    int tileRow = blockIdx.y, tileCol = blockIdx.x;
    if (SYM && tileRow * 128 >= tileCol * 256 + 256) return;   // entirely below diagonal

    __shared__ __align__(16) unsigned short As[2][128 * 32];
    __shared__ __align__(16) unsigned short Bs[2][256 * 32];
    int tid = threadIdx.x, lane = tid & 31, wid = tid >> 5;
    int wm = wid & 1, wn = wid >> 1;            // warp covers m:[wm*64,+64) n:[wn*64,+64)
    int rowBase = tileRow * 128, colBase = tileCol * 256;

    const int npc = Kseg / 32;
    const int NC = 3 * npc;

    auto koffA = [&](int c) { int p = c / npc, q = c - p * npc; return ((p == 2) ? Kseg : 0) + q * 32; };
    auto koffB = [&](int c) { int p = c / npc, q = c - p * npc; return ((p == 1) ? Kseg : 0) + q * 32; };

    auto load_stage = [&](int s, int c) {
        int ka = koffA(c), kb = koffB(c);
#pragma unroll
        for (int h = 0; h < 2; h++) {                       // A: 128 rows * 4 groups
            int i = tid + h * 256;
            int r = i >> 2, seg = i & 3;
            int dg = seg ^ (r & 3);
            uint32_t da = smem_u32(&As[s][r * 32 + dg * 8]);
            const unsigned short* sa = Ap + (size_t)(rowBase + r) * ldA + ka + seg * 8;
            asm volatile("cp.async.cg.shared.global [%0], [%1], 16;" :: "r"(da), "l"(sa));
        }
#pragma unroll
        for (int h = 0; h < 4; h++) {                       // B: 256 rows * 4 groups
            int i = tid + h * 256;
            int r = i >> 2, seg = i & 3;
            int dg = seg ^ (r & 3);
            uint32_t db = smem_u32(&Bs[s][r * 32 + dg * 8]);
            const unsigned short* sb = Bp + (size_t)(colBase + r) * ldB + kb + seg * 8;
            asm volatile("cp.async.cg.shared.global [%0], [%1], 16;" :: "r"(db), "l"(sb));
        }
        asm volatile("cp.async.commit_group;" ::: "memory");
    };

    float acc[4][8][4];
#pragma unroll
    for (int mi = 0; mi < 4; mi++)
#pragma unroll
        for (int ni = 0; ni < 8; ni++)
#pragma unroll
            for (int e = 0; e < 4; e++) acc[mi][ni][e] = 0.f;

    load_stage(0, 0);

    for (int c = 0; c < NC; c++) {
        int s = c & 1;
        if (c + 1 < NC) {
            load_stage(s ^ 1, c + 1);
            asm volatile("cp.async.wait_group 1;" ::: "memory");
        } else {
            asm volatile("cp.async.wait_group 0;" ::: "memory");
        }
        __syncthreads();

        const unsigned short* Ab = As[s];
        const unsigned short* Bb = Bs[s];
#pragma unroll
        for (int ks = 0; ks < 2; ks++) {
            uint32_t af[4][4];
#pragma unroll
            for (int mi = 0; mi < 4; mi++) {
                int row = wm * 64 + mi * 16 + (lane & 15);
                int cg = ks * 2 + (lane >> 4);
                uint32_t a = smem_u32(&Ab[row * 32 + ((cg ^ (row & 3)) << 3)]);
                asm volatile("ldmatrix.sync.aligned.m8n8.x4.shared.b16 {%0,%1,%2,%3}, [%4];"
                             : "=r"(af[mi][0]), "=r"(af[mi][1]), "=r"(af[mi][2]), "=r"(af[mi][3])
                             : "r"(a));
            }
            uint32_t bfr[8][2];
#pragma unroll
            for (int ni = 0; ni < 8; ni++) {
                int row = wn * 64 + ni * 8 + (lane & 7);
                int cg = ks * 2 + ((lane >> 3) & 1);
                uint32_t a = smem_u32(&Bb[row * 32 + ((cg ^ (row & 3)) << 3)]);
                asm volatile("ldmatrix.sync.aligned.m8n8.x2.shared.b16 {%0,%1}, [%2];"
                             : "=r"(bfr[ni][0]), "=r"(bfr[ni][1]) : "r"(a));
            }
#pragma unroll
            for (int mi = 0; mi < 4; mi++)
#pragma unroll
                for (int ni = 0; ni < 8; ni++) {
                    asm volatile(
                        "mma.sync.aligned.m16n8k16.row.col.f32.bf16.bf16.f32 "
                        "{%0,%1,%2,%3}, {%4,%5,%6,%7}, {%8,%9}, {%0,%1,%2,%3};"
                        : "+f"(acc[mi][ni][0]), "+f"(acc[mi][ni][1]),
                          "+f"(acc[mi][ni][2]), "+f"(acc[mi][ni][3])
                        : "r"(af[mi][0]), "r"(af[mi][1]), "r"(af[mi][2]), "r"(af[mi][3]),
                          "r"(bfr[ni][0]), "r"(bfr[ni][1]));
                }
        }
        __syncthreads();
    }

    // epilogue: c0,c1 -> (row l/4, cols 2*(l%4)+{0,1}); c2,c3 -> row +8
#pragma unroll
    for (int mi = 0; mi < 4; mi++) {
#pragma unroll
        for (int ni = 0; ni < 8; ni++) {
            int gm0 = rowBase + wm * 64 + mi * 16 + (lane >> 2);
            int gn0 = colBase + wn * 64 + ni * 8 + (lane & 3) * 2;
#pragma unroll
            for (int h = 0; h < 2; h++) {
                int gm = gm0 + h * 8;
#pragma unroll
                for (int e = 0; e < 2; e++) {
                    int gn = gn0 + e;
                    float v = acc[mi][ni][h * 2 + e];
                    if (MODE == 2) {
                        if (gn < Nreal)
                            C[(size_t)gm * ldc + gn] = fmaxf(v + aux[gn], 0.f);
                    } else {
                        float s2 = 2.f * v - aux[gm] - aux[gn];   // = -d^2
                        if (!SYM) {
                            C[(size_t)gm * ldc + gn] = s2;
                        } else {
                            if (gm <= gn) C[(size_t)gm * ldc + gn] = s2;
                            if (gm < gn)  C[(size_t)gn * ldc + gm] = s2;
                        }
                    }
                }
            }
        }
    }
}

// W [Kreal, Nreal] row-major -> packed B [Npad, 2*Kseg] (transpose + hi/lo split; zero-pads)
__global__ void pack_split_T(const float* __restrict__ W, int Kreal, int Nreal,
                             unsigned short* __restrict__ Y, int Kseg, int Npad) {
    __shared__ float t[32][33];
    int kb = blockIdx.x * 32, nb = blockIdx.y * 32;
    int tx = threadIdx.x, ty = threadIdx.y;  // 32 x 8
#pragma unroll
    for (int i = 0; i < 32; i += 8) {
        int k = kb + ty + i, nn = nb + tx;
        t[ty + i][tx] = (k < Kreal && nn < Nreal) ? W[(size_t)k * Nreal + nn] : 0.f;
    }
    __syncthreads();
#pragma unroll
    for (int i = 0; i < 32; i += 8) {
        int nn = nb + ty + i, k = kb + tx;
        if (nn < Npad && k < Kseg) {
            unsigned short h, l;
            split_bf16(t[tx][ty + i], h, l);
            Y[(size_t)nn * (2 * Kseg) + k] = h;
            Y[(size_t)nn * (2 * Kseg) + Kseg + k] = l;
        }
    }
}

// zero the pad columns [Kreal, Kseg) of a packed operand
__global__ void pad_pack(unsigned short* __restrict__ P, int Kreal, int Kseg, int rows) {
    int pad = Kseg - Kreal;
    int total = rows * pad;
    for (int i = blockIdx.x * blockDim.x + threadIdx.x; i < total;
         i += gridDim.x * blockDim.x) {
        int r = i / pad, k = Kreal + i % pad;
        size_t base = (size_t)r * (2 * Kseg) + k;
        P[base] = 0;
        P[base + Kseg] = 0;
    }
}

// pack fp32 [NPTS, C1] into pp2 slice (hi/lo)
__global__ void pack_slice(const float* __restrict__ src, unsigned short* __restrict__ P,
                           int slice) {
    int i = blockIdx.x * blockDim.x + threadIdx.x;
    if (i < NPTS * C1) {
        int r = i / C1, c = i % C1;
        unsigned short h, l;
        split_bf16(src[i], h, l);
        size_t base = (size_t)r * (2 * KSEG2) + slice * C1 + c;
        P[base] = h;
        P[base + KSEG2] = l;
    }
}

// ================= small helper kernels =================
__global__ void rowsq_kernel(const float* __restrict__ X, float* __restrict__ out,
                             int M, int F) {
    int row = blockIdx.x;
    int tid = threadIdx.x;
    float acc = 0.f;
    for (int j = tid; j < F; j += blockDim.x) {
        float v = X[(size_t)row * F + j];
        acc += v * v;
    }
    __shared__ float red[256];
    red[tid] = acc; __syncthreads();
    for (int s = 128; s > 0; s >>= 1) {
        if (tid < s) red[tid] += red[tid + s];
        __syncthreads();
    }
    if (tid == 0) out[row] = red[0];
}

// legacy small SGEMM with explicit leading dims.
// mode 0: C=acc | 1: C+=acc | 2: C=relu(acc+aux[n])
// mode 4: C = 2*acc - aux[m] - aux[n]  (= -d^2; exp deferred)
// mode 5: mode 2 + pack hi/lo into P [gm, 2*Ksg]
#define BM 64
#define BN 64
#define BK 16
__global__ void sgemm(int M, int N, int K,
                      const float* __restrict__ A, int lda,
                      const float* __restrict__ B, int ldb,
                      float* C, int ldc, int transB, int mode,
                      const float* __restrict__ aux,
                      unsigned short* __restrict__ P, int Ksg) {
    __shared__ float As[BK][BM];
    __shared__ float Bs[BK][BN];
    int tid = threadIdx.x;
    int tx = tid & 15, ty = tid >> 4;
    int rowBase = blockIdx.y * BM;
    int colBase = blockIdx.x * BN;

    float acc[4][4];
#pragma unroll
    for (int i = 0; i < 4; i++)
#pragma unroll
        for (int j = 0; j < 4; j++) acc[i][j] = 0.f;

    for (int k0 = 0; k0 < K; k0 += BK) {
#pragma unroll
        for (int l = 0; l < 4; l++) {
            int idx = tid + l * 256;
            int m = idx >> 4, kk = idx & 15;
            int gm = rowBase + m, gk = k0 + kk;
            As[kk][m] = (gm < M && gk < K) ? A[(size_t)gm * lda + gk] : 0.f;
        }
        if (!transB) {
#pragma unroll
            for (int l = 0; l < 4; l++) {
                int idx = tid + l * 256;
                int kk = idx >> 6, n = idx & 63;
                int gn = colBase + n, gk = k0 + kk;
                Bs[kk][n] = (gk < K && gn < N) ? B[(size_t)gk * ldb + gn] : 0.f;
            }
        } else {
#pragma unroll
            for (int l = 0; l < 4; l++) {
                int idx = tid + l * 256;
                int n = idx >> 4, kk = idx & 15;
                int gn = colBase + n, gk = k0 + kk;
                Bs[kk][n] = (gk < K && gn < N) ? B[(size_t)gn * ldb + gk] : 0.f;
            }
        }
        __syncthreads();
#pragma unroll
        for (int k = 0; k < BK; k++) {
            float ra[4], rb[4];
#pragma unroll
            for (int i = 0; i < 4; i++) ra[i] = As[k][ty * 4 + i];
#pragma unroll
            for (int j = 0; j < 4; j++) rb[j] = Bs[k][tx * 4 + j];
#pragma unroll
            for (int i = 0; i < 4; i++)
#pragma unroll
                for (int j = 0; j < 4; j++) acc[i][j] += ra[i] * rb[j];
        }
        __syncthreads();
    }

#pragma unroll
    for (int i = 0; i < 4; i++) {
        int gm = rowBase + ty * 4 + i;
        if (gm >= M) continue;
#pragma unroll
        for (int j = 0; j < 4; j++) {
            int gn = colBase + tx * 4 + j;
            if (gn >= N) continue;
            size_t o = (size_t)gm * ldc + gn;
            float v = acc[i][j];
            if (mode == 0) {
                C[o] = v;
            } else if (mode == 1) {
                C[o] += v;
            } else if (mode == 2) {
                C[o] = fmaxf(v + aux[gn], 0.f);
            } else if (mode == 4) {
                C[o] = 2.f * v - aux[gm] - aux[gn];
            } else {  // mode 5
                float r = fmaxf(v + aux[gn], 0.f);
                C[o] = r;
                unsigned short h, l;
                split_bf16(r, h, l);
                size_t base = (size_t)gm * (2 * Ksg) + gn;
                P[base] = h;
                P[base + Ksg] = l;
            }
        }
    }
}

// ================= exact top-k (k=40) on scores s=-d^2; kval = exp(s) =================
__global__ void topk_kernel(const float* __restrict__ W, int* __restrict__ kidx,
                            float* __restrict__ kval, float* __restrict__ dinv, int n) {
    __shared__ float sv[NPTS];
    __shared__ float rv[256];
    __shared__ int   ri[256];
    int row = blockIdx.x;
    int tid = threadIdx.x;
    for (int j = tid; j < n; j += 256) sv[j] = W[(size_t)row * n + j];
    __syncthreads();
    float rowsum = 0.f;
    for (int it = 0; it < KNN; it++) {
        float best = -3e38f; int bidx = n;
        for (int j = tid; j < n; j += 256) {
            float v = sv[j];
            if (v > best) { best = v; bidx = j; }
        }
        rv[tid] = best; ri[tid] = bidx;
        __syncthreads();
        for (int s = 128; s > 0; s >>= 1) {
            if (tid < s) {
                if (rv[tid + s] > rv[tid] ||
                    (rv[tid + s] == rv[tid] && ri[tid + s] < ri[tid])) {
                    rv[tid] = rv[tid + s]; ri[tid] = ri[tid + s];
                }
            }
            __syncthreads();
        }
        if (tid == 0) {
            float ev = expf(rv[0]);
            kidx[row * KNN + it] = ri[0];
            kval[row * KNN + it] = ev;
            sv[ri[0]] = -3e38f;
            rowsum += ev;
        }
        __syncthreads();
    }
    if (tid == 0) dinv[row] = 1.f / sqrtf(rowsum);
}

// ================= sparse Laplacian apply (strided I/O) =================
// mode 0: Y = L X ; mode 1: Y = 2 L X - Prev
__global__ void spmm_lap(const float* __restrict__ X, int ldx,
                         const int* __restrict__ kidx,
                         const float* __restrict__ kval, const float* __restrict__ dinv,
                         float* __restrict__ Y, int ldy,
                         const float* __restrict__ Prev, int ldp,
                         int F, int mode) {
    int r = blockIdx.x;
    __shared__ int   sidx[KNN];
    __shared__ float sw[KNN];
    int tid = threadIdx.x;
    if (tid < KNN) {
        int c = kidx[r * KNN + tid];
        sidx[tid] = c;
        sw[tid] = kval[r * KNN + tid] * dinv[r] * dinv[c];
    }
    __syncthreads();
    for (int c = tid; c < F; c += blockDim.x) {
        float acc = X[(size_t)r * ldx + c];
#pragma unroll 8
        for (int j = 0; j < KNN; j++)
            acc -= sw[j] * X[(size_t)sidx[j] * ldx + c];
        if (mode) acc = 2.f * acc - Prev[(size_t)r * ldp + c];
        Y[(size_t)r * ldy + c] = acc;
    }
}

// sparse Laplacian + fused bf16 packing into pp2 slice (F = C1 fixed)
__global__ void spmm_pack(const float* __restrict__ X,
                          const int* __restrict__ kidx,
                          const float* __restrict__ kval, const float* __restrict__ dinv,
                          float* __restrict__ Y, const float* __restrict__ Prev,
                          int mode, unsigned short* __restrict__ P, int slice) {
    int r = blockIdx.x;
    __shared__ int   sidx[KNN];
    __shared__ float sw[KNN];
    int tid = threadIdx.x;
    if (tid < KNN) {
        int c = kidx[r * KNN + tid];
        sidx[tid] = c;
        sw[tid] = kval[r * KNN + tid] * dinv[r] * dinv[c];
    }
    __syncthreads();
    for (int c = tid; c < C1; c += blockDim.x) {
        float acc = X[(size_t)r * C1 + c];
#pragma unroll 8
        for (int j = 0; j < KNN; j++)
            acc -= sw[j] * X[(size_t)sidx[j] * C1 + c];
        if (mode) acc = 2.f * acc - Prev[(size_t)r * C1 + c];
        Y[(size_t)r * C1 + c] = acc;
        unsigned short h, l;
        split_bf16(acc, h, l);
        size_t base = (size_t)r * (2 * KSEG2) + slice * C1 + c;
        P[base] = h;
        P[base + KSEG2] = l;
    }
}

__global__ void build_xhat1(const float* __restrict__ x, const float* __restrict__ m1,
                            const float* __restrict__ t2, float* __restrict__ xh, int n) {
    int i = blockIdx.x * blockDim.x + threadIdx.x;
    if (i < n * 6) {
        int r = i / 6, f = i % 6;
        xh[r * 18 + f] = x[i];
        xh[r * 18 + 6 + f] = m1[i];
        xh[r * 18 + 12 + f] = 2.f * t2[i] - x[i];
    }
}

// Reeb Chebyshev fix on concatenated layout: rcat[r, 2000+c] = 2*rcat[r, 2000+c] - rcat[r, c]
__global__ void cheb_fix_reeb(float* __restrict__ rcat) {
    int i = blockIdx.x * blockDim.x + threadIdx.x;
    if (i < NRB * C1) {
        int r = i / C1, c = i % C1;
        rcat[r * KREEB + 2000 + c] = 2.f * rcat[r * KREEB + 2000 + c] - rcat[r * KREEB + c];
    }
}

__global__ void sccpool(const float* __restrict__ out, const int* __restrict__ sccs,
                        float* __restrict__ rcat) {
    int r = blockIdx.y;
    int c = blockIdx.x * 256 + threadIdx.x;
    if (c < C1) {
        float m = -3e38f;
        for (int s = 0; s < SCC_S; s++) {
            int n = sccs[r * SCC_S + s];
            m = fmaxf(m, out[(size_t)n * C1 + c]);
        }
        rcat[r * KREEB + c] = m;   // slice 0 = vfr
    }
}

__global__ void colmax(const float* __restrict__ M, float* __restrict__ outv,
                       int R, int Ncol, int off) {
    int c = blockIdx.x * 256 + threadIdx.x;
    if (c < Ncol) {
        float m = -3e38f;
        for (int r = 0; r < R; r++) m = fmaxf(m, M[(size_t)r * Ncol + c]);
        outv[off + c] = m;
    }
}

// two-stage column max over 4096 rows
__global__ void colmax_p1(const float* __restrict__ M, float* __restrict__ part, int Ncol) {
    int chunk = blockIdx.y;
    int c = blockIdx.x * 256 + threadIdx.x;
    if (c < Ncol) {
        float m = -3e38f;
        int r0 = chunk * 128;
        for (int r = r0; r < r0 + 128; r++) m = fmaxf(m, M[(size_t)r * Ncol + c]);
        part[(size_t)chunk * Ncol + c] = m;
    }
}
__global__ void colmax_p2(const float* __restrict__ part, float* __restrict__ outv,
                          int Ncol, int off) {
    int c = blockIdx.x * 256 + threadIdx.x;
    if (c < Ncol) {
        float m = -3e38f;
        for (int ch = 0; ch < 32; ch++) m = fmaxf(m, part[(size_t)ch * Ncol + c]);
        outv[off + c] = m;
    }
}

// two-stage regularizer: ss += || O^T @ Mv ||_F^2
__global__ void reg_p1(const float* __restrict__ O, const float* __restrict__ Mv,
                       float* __restrict__ part, int C) {
    int chunk = blockIdx.y;
    int c = blockIdx.x * 256 + threadIdx.x;
    __shared__ float sm[256 * 6];
    int n0 = chunk * 256;
    for (int i = threadIdx.x; i < 256 * 6; i += 256) sm[i] = Mv[n0 * 6 + i];
    __syncthreads();
    if (c < C) {
        float acc[6] = {0, 0, 0, 0, 0, 0};
        for (int t = 0; t < 256; t++) {
            float v = O[(size_t)(n0 + t) * C + c];
#pragma unroll
            for (int f = 0; f < 6; f++) acc[f] += v * sm[t * 6 + f];
        }
#pragma unroll
        for (int f = 0; f < 6; f++) part[((size_t)chunk * C + c) * 6 + f] = acc[f];
    }
}
__global__ void reg_p2(const float* __restrict__ part, float* ss, int C) {
    int c = blockIdx.x * 256 + threadIdx.x;
    if (c < C) {
        float s = 0.f;
#pragma unroll
        for (int f = 0; f < 6; f++) {
            float a = 0.f;
            for (int ch = 0; ch < 16; ch++) a += part[((size_t)ch * C + c) * 6 + f];
            s += a * a;
        }
        atomicAdd(ss, s);
    }
}

__global__ void fc_kernel(const float* __restrict__ in, const float* __restrict__ Wf,
                          const float* __restrict__ bf, float* __restrict__ outv,
                          int In, int Out, int doRelu) {
    __shared__ float sIn[2048];
    for (int i = threadIdx.x; i < In; i += blockDim.x) sIn[i] = in[i];
    __syncthreads();
    int o = threadIdx.x;
    if (o < Out) {
        float a = bf[o];
        for (int i = 0; i < In; i++) a += sIn[i] * Wf[(size_t)i * Out + o];
        outv[o] = doRelu ? fmaxf(a, 0.f) : a;
    }
}

__global__ void finalize2(const float* __restrict__ ss,
                          const float* __restrict__ fc1w, const float* __restrict__ fc1b,
                          const float* __restrict__ fc2w, const float* __restrict__ fc2b,
                          const float* __restrict__ fc3w, const float* __restrict__ fc3b,
                          float* out) {
    __shared__ float red[256];
    int tid = threadIdx.x;
    float s1, s2, s3;
    float a = 0.f;
    for (int i = tid; i < 2000; i += 256) { float v = fc1w[(size_t)i * 512]; a += v * v; }
    red[tid] = a; __syncthreads();
    for (int s = 128; s > 0; s >>= 1) { if (tid < s) red[tid] += red[tid + s]; __syncthreads(); }
    s1 = red[0]; __syncthreads();
    a = 0.f;
    for (int i = tid; i < 512; i += 256) { float v = fc2w[(size_t)i * 128]; a += v * v; }
    red[tid] = a; __syncthreads();
    for (int s = 128; s > 0; s >>= 1) { if (tid < s) red[tid] += red[tid + s]; __syncthreads(); }
    s2 = red[0]; __syncthreads();
    a = 0.f;
    for (int i = tid; i < 128; i += 256) { float v = fc3w[(size_t)i * 40]; a += v * v; }
    red[tid] = a; __syncthreads();
    for (int s = 128; s > 0; s >>= 1) { if (tid < s) red[tid] += red[tid + s]; __syncthreads(); }
    s3 = red[0];
    if (tid == 0) {
        out[40] = sqrtf(ss[0]);
        out[41] = sqrtf(ss[1]);
        out[42] = s1;
        out[43] = fc1b[0] * fc1b[0];
        out[44] = s2;
        out[45] = fc2b[0] * fc2b[0];
        out[46] = s3;
        out[47] = fc3b[0] * fc3b[0];
    }
}

static inline dim3 gemmGrid(int M, int N) {
    return dim3((N + BN - 1) / BN, (M + BM - 1) / BM);
}

extern "C" void kernel_launch(void* const* d_in, const int* in_sizes, int n_in,
                              void* d_out, int out_size) {
    const float* x     = (const float*)d_in[0];
    const float* Lr    = (const float*)d_in[5];
    const int*   sccs  = (const int*)d_in[6];
    const float* W1    = (const float*)d_in[7];
    const float* b1    = (const float*)d_in[8];
    const float* W2    = (const float*)d_in[9];
    const float* b2    = (const float*)d_in[10];
    const float* Wr    = (const float*)d_in[11];
    const float* br    = (const float*)d_in[12];
    const float* fc1w  = (const float*)d_in[13];
    const float* fc1b  = (const float*)d_in[14];
    const float* fc2w  = (const float*)d_in[15];
    const float* fc2b  = (const float*)d_in[16];
    const float* fc3w  = (const float*)d_in[17];
    const float* fc3b  = (const float*)d_in[18];
    float* out = (float*)d_out;

    float *pA, *pout, *pout2, *pTxA, *pTxB, *pxh, *pM1, *pM2, *pT2v;
    float *psq, *psq2, *pdinv, *pkval, *prcat, *poutr, *pfeat, *ph1, *ph2, *pss;
    float *pcm, *prg;
    int *pkidx;
    unsigned short *pp1, *pp2, *ppb;
    cudaGetSymbolAddress((void**)&pA, g_A);
    cudaGetSymbolAddress((void**)&pout, g_out);
    cudaGetSymbolAddress((void**)&pout2, g_out2);
    cudaGetSymbolAddress((void**)&pTxA, g_TxA);
    cudaGetSymbolAddress((void**)&pTxB, g_TxB);
    cudaGetSymbolAddress((void**)&pxh, g_xhat1);
    cudaGetSymbolAddress((void**)&pM1, g_M1);
    cudaGetSymbolAddress((void**)&pM2, g_M2);
    cudaGetSymbolAddress((void**)&pT2v, g_T2v);
    cudaGetSymbolAddress((void**)&psq, g_sq);
    cudaGetSymbolAddress((void**)&psq2, g_sq2);
    cudaGetSymbolAddress((void**)&pdinv, g_dinv);
    cudaGetSymbolAddress((void**)&pkidx, g_kidx);
    cudaGetSymbolAddress((void**)&pkval, g_kval);
    cudaGetSymbolAddress((void**)&prcat, g_rcat);
    cudaGetSymbolAddress((void**)&poutr, g_outr);
    cudaGetSymbolAddress((void**)&pfeat, g_feat);
    cudaGetSymbolAddress((void**)&ph1, g_h1);
    cudaGetSymbolAddress((void**)&ph2, g_h2);
    cudaGetSymbolAddress((void**)&pss, g_ss);
    cudaGetSymbolAddress((void**)&pcm, g_cmpart);
    cudaGetSymbolAddress((void**)&prg, g_regpart);
    cudaGetSymbolAddress((void**)&pp1, g_packA1);
    cudaGetSymbolAddress((void**)&pp2, g_packA2);
    cudaGetSymbolAddress((void**)&ppb, g_packB2);

    cudaMemsetAsync(pss, 0, 2 * sizeof(float), 0);

    // ===== graph 1 (K=6 features; SIMT fp32; scores s=-d^2, exp deferred) =====
    rowsq_kernel<<<NPTS, 256>>>(x, psq, NPTS, FIN);
    sgemm<<<gemmGrid(NPTS, NPTS), 256>>>(NPTS, NPTS, FIN, x, FIN, x, FIN, pA, NPTS,
                                         1, 4, psq, nullptr, 0);
    topk_kernel<<<NPTS, 256>>>(pA, pkidx, pkval, pdinv, NPTS);

    spmm_lap<<<NPTS, 64>>>(x, FIN, pkidx, pkval, pdinv, pM1, FIN, nullptr, 0, FIN, 0);
    spmm_lap<<<NPTS, 64>>>(pM1, FIN, pkidx, pkval, pdinv, pT2v, FIN, nullptr, 0, FIN, 0);
    build_xhat1<<<(NPTS * 6 + 255) / 256, 256>>>(x, pM1, pT2v, pxh, NPTS);
    // conv1 with fused hi/lo pack into adjacency operand pp1
    sgemm<<<gemmGrid(NPTS, C1), 256>>>(NPTS, C1, 18, pxh, 18, W1, C1, pout, C1,
                                       0, 5, b1, pp1, KSEG1);
    pad_pack<<<384, 256>>>(pp1, C1, KSEG1, NPTS);

    reg_p1<<<dim3(4, 16), 256>>>(pout, pM1, prg, C1);
    reg_p2<<<4, 256>>>(prg, pss + 0, C1);
    sccpool<<<dim3((C1 + 255) / 256, NRB), 256>>>(pout, sccs, prcat);

    // W2^T pack (covers all padding itself)
    pack_split_T<<<dim3((KSEG2 + 31) / 32, NPAD2 / 32), dim3(32, 8)>>>(W2, KCAT, C2, ppb, KSEG2, NPAD2);

    // ===== graph 2: adjacency via symmetric tensor-core GEMM (128x256 tiles) =====
    rowsq_kernel<<<NPTS, 256>>>(pout, psq2, NPTS, C1);
    gemm_mma<4, 1><<<dim3(16, 32), 256>>>(pp1, 2 * KSEG1, pp1, 2 * KSEG1,
                                          KSEG1, NPTS, pA, NPTS, psq2);
    topk_kernel<<<NPTS, 256>>>(pA, pkidx, pkval, pdinv, NPTS);
    spmm_lap<<<NPTS, 64>>>(x, FIN, pkidx, pkval, pdinv, pM2, FIN, nullptr, 0, FIN, 0);

    // Chebyshev basis T0..T5 packed directly into pp2 (fp32 recursion in TxA/TxB)
    pack_slice<<<(NPTS * C1 + 255) / 256, 256>>>(pout, pp2, 0);                        // T0
    pad_pack<<<256, 256>>>(pp2, KCAT, KSEG2, NPTS);
    spmm_pack<<<NPTS, 256>>>(pout, pkidx, pkval, pdinv, pTxA, nullptr, 0, pp2, 1);     // T1
    spmm_pack<<<NPTS, 256>>>(pTxA, pkidx, pkval, pdinv, pTxB, pout, 1, pp2, 2);        // T2
    spmm_pack<<<NPTS, 256>>>(pTxB, pkidx, pkval, pdinv, pTxA, pTxA, 1, pp2, 3);        // T3
    spmm_pack<<<NPTS, 256>>>(pTxA, pkidx, pkval, pdinv, pTxB, pTxB, 1, pp2, 4);        // T4
    spmm_pack<<<NPTS, 256>>>(pTxB, pkidx, pkval, pdinv, pTxA, pTxA, 1, pp2, 5);        // T5

    // conv2 via tensor cores: out2 = relu(xhat2 @ W2 + b2), K=6016 padded
    gemm_mma<2, 0><<<dim3(NPAD2 / 256, 32), 256>>>(pp2, 2 * KSEG2, ppb, 2 * KSEG2,
                                                   KSEG2, C2, pout2, C2, b2);

    reg_p1<<<dim3(4, 16), 256>>>(pout2, pM2, prg, C2);
    reg_p2<<<4, 256>>>(prg, pss + 1, C2);
    colmax_p1<<<dim3(4, 32), 256>>>(pout2, pcm, C2);
    colmax_p2<<<4, 256>>>(pcm, pfeat, C2, C2);

    // ===== Reeb branch: concatenated basis [vfr|Tr1|Tr2] then one K=3000 GEMM =====
    sgemm<<<gemmGrid(NRB, C1), 256>>>(NRB, C1, NRB, Lr, NRB, prcat, KREEB, prcat + 1000, KREEB,
                                      0, 0, nullptr, nullptr, 0);
    sgemm<<<gemmGrid(NRB, C1), 256>>>(NRB, C1, NRB, Lr, NRB, prcat + 1000, KREEB, prcat + 2000, KREEB,
                                      0, 0, nullptr, nullptr, 0);
    cheb_fix_reeb<<<(NRB * C1 + 255) / 256, 256>>>(prcat);
    sgemm<<<gemmGrid(NRB, C2), 256>>>(NRB, C2, KREEB, prcat, KREEB, Wr, C2, poutr, C2,
                                      0, 2, br, nullptr, 0);
    colmax<<<(C2 + 255) / 256, 256>>>(poutr, pfeat, NRB, C2, 0);

    // ===== FC head =====
    fc_kernel<<<1, 512>>>(pfeat, fc1w, fc1b, ph1, 2 * C2, 512, 1);
    fc_kernel<<<1, 128>>>(ph1, fc2w, fc2b, ph2, 512, 128, 1);
    fc_kernel<<<1, 64>>>(ph2, fc3w, fc3b, out, 128, NCLS, 0);

    finalize2<<<1, 256>>>(pss, fc1w, fc1b, fc2w, fc2b, fc3w, fc3b, out);

    (void)in_sizes; (void)n_in; (void)out_size;
}

// round 16
// speedup vs baseline: 1.0923x; 1.0923x over previous
#include <cuda_runtime.h>
#include <cuda_bf16.h>
#include <math.h>
#include <stdint.h>

#define NPTS 4096
#define FIN  6
#define C1   1000
#define C2   1000
#define KNN  40
#define NRB  20
#define SCC_S 205
#define NCLS 40
#define KCAT 6000          // 6 * C1 concatenated Chebyshev basis
#define KSEG1 1024         // padded K, adjacency (1000 -> 1024)
#define KSEG2 6016         // padded K, conv2 (6000 -> 6016)
#define NPAD2 1024         // padded N for conv2 B operand
#define KREEB 3000         // concatenated Reeb basis [vfr|Tr1|Tr2]

// ---------------- scratch (device globals; no allocation) ----------------
__device__ float g_A[(size_t)NPTS * NPTS];       // adjacency scores s = -d^2 (graph 2 only)
__device__ float g_out [(size_t)NPTS * C1];
__device__ float g_out2[(size_t)NPTS * C2];
__device__ float g_TxA [(size_t)NPTS * C1];      // Chebyshev fp32 ping
__device__ float g_TxB [(size_t)NPTS * C1];      // Chebyshev fp32 pong
__device__ float g_xhat1[(size_t)NPTS * 18];
__device__ float g_M1[NPTS * FIN];
__device__ float g_M2[NPTS * FIN];
__device__ float g_T2v[NPTS * FIN];
__device__ float g_sq [NPTS];
__device__ float g_sq2[NPTS];
__device__ float g_dinv[NPTS];
__device__ int   g_kidx[NPTS * KNN];
__device__ float g_kval[NPTS * KNN];
__device__ float g_rcat[NRB * KREEB];            // [vfr | Tr1 | Tr2] concatenated
__device__ float g_outr[NRB * C1];
__device__ float g_feat[2 * C2];
__device__ float g_h1[512];
__device__ float g_h2[128];
__device__ float g_ss[2];
__device__ float g_cmpart[32 * C2];
__device__ float g_regpart[16 * C1 * 6];
// bf16 hi/lo packed operands: row-major [rows, 2*Kseg] (hi at k, lo at Kseg+k)
__device__ __align__(16) unsigned short g_packA1[(size_t)NPTS * 2 * KSEG1];   // out split
__device__ __align__(16) unsigned short g_packA2[(size_t)NPTS * 2 * KSEG2];   // xhat2 split
__device__ __align__(16) unsigned short g_packB2[(size_t)NPAD2 * 2 * KSEG2];  // W2^T split

// ================= helpers =================
__device__ __forceinline__ uint32_t smem_u32(const void* p) {
    uint32_t a;
    asm("{ .reg .u64 t; cvta.to.shared.u64 t, %1; cvt.u32.u64 %0, t; }" : "=r"(a) : "l"(p));
    return a;
}
__device__ __forceinline__ void split_bf16(float v, unsigned short& h, unsigned short& l) {
    __nv_bfloat16 hb = __float2bfloat16(v);
    float lo = v - __bfloat162float(hb);
    __nv_bfloat16 lb = __float2bfloat16(lo);
    h = *(unsigned short*)&hb;
    l = *(unsigned short*)&lb;
}

// ============ tensor-core GEMM: C = A2 @ B2^T via bf16 hi/lo 3-pass ============
// (round-13 proven configuration: 128x128x32 tiles, 8 warps 64x32, 3-stage
//  cp.async in 48KB static smem with XOR swizzle — do not change)
// MODE 4: C = 2*acc - aux[gm] - aux[gn]  (= -d^2; exp deferred to topk)
//         SYM=1: only upper-tri tiles computed; mirror-stored.
// MODE 2: C = relu(acc + aux[gn]) for gn < Nreal    (bias + relu)
template<int MODE, int SYM>
__global__ void __launch_bounds__(256)
gemm_mma(const unsigned short* __restrict__ Ap, int ldA,
         const unsigned short* __restrict__ Bp, int ldB,
         int Kseg, int Nreal, float* __restrict__ C, int ldc,
         const float* __restrict__ aux) {
    int tileRow = blockIdx.y, tileCol = blockIdx.x;
    if (SYM && tileRow > tileCol) return;

    __shared__ __align__(16) unsigned short As[3][128 * 32];
    __shared__ __align__(16) unsigned short Bs[3][128 * 32];
    int tid = threadIdx.x, lane = tid & 31, wid = tid >> 5;
    int wm = wid & 1, wn = wid >> 1;            // warp covers m:[wm*64,+64) n:[wn*32,+32)
    int rowBase = tileRow * 128, colBase = tileCol * 128;

    const int npc = Kseg / 32;
    const int NC = 3 * npc;

    auto koffA = [&](int c) { int p = c / npc, q = c - p * npc; return ((p == 2) ? Kseg : 0) + q * 32; };
    auto koffB = [&](int c) { int p = c / npc, q = c - p * npc; return ((p == 1) ? Kseg : 0) + q * 32; };

    auto load_stage = [&](int s, int c) {
        int ka = koffA(c), kb = koffB(c);
#pragma unroll
        for (int h = 0; h < 2; h++) {
            int i = tid + h * 256;
            int r = i >> 2, seg = i & 3;
            int dg = seg ^ (r & 3);                       // swizzled 16B group
            uint32_t da = smem_u32(&As[s][r * 32 + dg * 8]);
            const unsigned short* sa = Ap + (size_t)(rowBase + r) * ldA + ka + seg * 8;
            asm volatile("cp.async.cg.shared.global [%0], [%1], 16;" :: "r"(da), "l"(sa));
            uint32_t db = smem_u32(&Bs[s][r * 32 + dg * 8]);
            const unsigned short* sb = Bp + (size_t)(colBase + r) * ldB + kb + seg * 8;
            asm volatile("cp.async.cg.shared.global [%0], [%1], 16;" :: "r"(db), "l"(sb));
        }
        asm volatile("cp.async.commit_group;" ::: "memory");
    };

    float acc[4][4][4];
#pragma unroll
    for (int mi = 0; mi < 4; mi++)
#pragma unroll
        for (int ni = 0; ni < 4; ni++)
#pragma unroll
            for (int e = 0; e < 4; e++) acc[mi][ni][e] = 0.f;

    load_stage(0, 0);
    load_stage(1, 1);

    for (int c = 0; c < NC; c++) {
        int s = c % 3;
        if (c + 2 < NC) {
            load_stage((c + 2) % 3, c + 2);
            asm volatile("cp.async.wait_group 2;" ::: "memory");
        } else if (c + 1 < NC) {
            asm volatile("cp.async.wait_group 1;" ::: "memory");
        } else {
            asm volatile("cp.async.wait_group 0;" ::: "memory");
        }
        __syncthreads();

        const unsigned short* Ab = As[s];
        const unsigned short* Bb = Bs[s];
#pragma unroll
        for (int ks = 0; ks < 2; ks++) {
            uint32_t af[4][4];
#pragma unroll
            for (int mi = 0; mi < 4; mi++) {
                int row = wm * 64 + mi * 16 + (lane & 15);
                int cg = ks * 2 + (lane >> 4);
                uint32_t a = smem_u32(&Ab[row * 32 + ((cg ^ (row & 3)) << 3)]);
                asm volatile("ldmatrix.sync.aligned.m8n8.x4.shared.b16 {%0,%1,%2,%3}, [%4];"
                             : "=r"(af[mi][0]), "=r"(af[mi][1]), "=r"(af[mi][2]), "=r"(af[mi][3])
                             : "r"(a));
            }
            uint32_t bfr[4][2];
#pragma unroll
            for (int ni = 0; ni < 4; ni++) {
                int row = wn * 32 + ni * 8 + (lane & 7);
                int cg = ks * 2 + ((lane >> 3) & 1);
                uint32_t a = smem_u32(&Bb[row * 32 + ((cg ^ (row & 3)) << 3)]);
                asm volatile("ldmatrix.sync.aligned.m8n8.x2.shared.b16 {%0,%1}, [%2];"
                             : "=r"(bfr[ni][0]), "=r"(bfr[ni][1]) : "r"(a));
            }
#pragma unroll
            for (int mi = 0; mi < 4; mi++)
#pragma unroll
                for (int ni = 0; ni < 4; ni++) {
                    asm volatile(
                        "mma.sync.aligned.m16n8k16.row.col.f32.bf16.bf16.f32 "
                        "{%0,%1,%2,%3}, {%4,%5,%6,%7}, {%8,%9}, {%0,%1,%2,%3};"
                        : "+f"(acc[mi][ni][0]), "+f"(acc[mi][ni][1]),
                          "+f"(acc[mi][ni][2]), "+f"(acc[mi][ni][3])
                        : "r"(af[mi][0]), "r"(af[mi][1]), "r"(af[mi][2]), "r"(af[mi][3]),
                          "r"(bfr[ni][0]), "r"(bfr[ni][1]));
                }
        }
        __syncthreads();
    }

    // epilogue: c0,c1 -> (row l/4, cols 2*(l%4)+{0,1}); c2,c3 -> row +8
#pragma unroll
    for (int mi = 0; mi < 4; mi++) {
#pragma unroll
        for (int ni = 0; ni < 4; ni++) {
            int gm0 = rowBase + wm * 64 + mi * 16 + (lane >> 2);
            int gn0 = colBase + wn * 32 + ni * 8 + (lane & 3) * 2;
#pragma unroll
            for (int h = 0; h < 2; h++) {
                int gm = gm0 + h * 8;
#pragma unroll
                for (int e = 0; e < 2; e++) {
                    int gn = gn0 + e;
                    float v = acc[mi][ni][h * 2 + e];
                    if (MODE == 2) {
                        if (gn < Nreal)
                            C[(size_t)gm * ldc + gn] = fmaxf(v + aux[gn], 0.f);
                    } else {
                        float s2 = 2.f * v - aux[gm] - aux[gn];   // = -d^2
                        C[(size_t)gm * ldc + gn] = s2;
                        if (SYM && tileRow != tileCol)
                            C[(size_t)gn * ldc + gm] = s2;
                    }
                }
            }
        }
    }
}

// W [Kreal, Nreal] row-major -> packed B [Npad, 2*Kseg] (transpose + hi/lo split; zero-pads)
__global__ void pack_split_T(const float* __restrict__ W, int Kreal, int Nreal,
                             unsigned short* __restrict__ Y, int Kseg, int Npad) {
    __shared__ float t[32][33];
    int kb = blockIdx.x * 32, nb = blockIdx.y * 32;
    int tx = threadIdx.x, ty = threadIdx.y;  // 32 x 8
#pragma unroll
    for (int i = 0; i < 32; i += 8) {
        int k = kb + ty + i, nn = nb + tx;
        t[ty + i][tx] = (k < Kreal && nn < Nreal) ? W[(size_t)k * Nreal + nn] : 0.f;
    }
    __syncthreads();
#pragma unroll
    for (int i = 0; i < 32; i += 8) {
        int nn = nb + ty + i, k = kb + tx;
        if (nn < Npad && k < Kseg) {
            unsigned short h, l;
            split_bf16(t[tx][ty + i], h, l);
            Y[(size_t)nn * (2 * Kseg) + k] = h;
            Y[(size_t)nn * (2 * Kseg) + Kseg + k] = l;
        }
    }
}

// zero the pad columns [Kreal, Kseg) of a packed operand
__global__ void pad_pack(unsigned short* __restrict__ P, int Kreal, int Kseg, int rows) {
    int pad = Kseg - Kreal;
    int total = rows * pad;
    for (int i = blockIdx.x * blockDim.x + threadIdx.x; i < total;
         i += gridDim.x * blockDim.x) {
        int r = i / pad, k = Kreal + i % pad;
        size_t base = (size_t)r * (2 * Kseg) + k;
        P[base] = 0;
        P[base + Kseg] = 0;
    }
}

// pack fp32 [NPTS, C1] into pp2 slice (hi/lo)
__global__ void pack_slice(const float* __restrict__ src, unsigned short* __restrict__ P,
                           int slice) {
    int i = blockIdx.x * blockDim.x + threadIdx.x;
    if (i < NPTS * C1) {
        int r = i / C1, c = i % C1;
        unsigned short h, l;
        split_bf16(src[i], h, l);
        size_t base = (size_t)r * (2 * KSEG2) + slice * C1 + c;
        P[base] = h;
        P[base + KSEG2] = l;
    }
}

// ================= small helper kernels =================
__global__ void rowsq_kernel(const float* __restrict__ X, float* __restrict__ out,
                             int M, int F) {
    int row = blockIdx.x;
    int tid = threadIdx.x;
    float acc = 0.f;
    for (int j = tid; j < F; j += blockDim.x) {
        float v = X[(size_t)row * F + j];
        acc += v * v;
    }
    __shared__ float red[256];
    red[tid] = acc; __syncthreads();
    for (int s = 128; s > 0; s >>= 1) {
        if (tid < s) red[tid] += red[tid + s];
        __syncthreads();
    }
    if (tid == 0) out[row] = red[0];
}

// legacy small SGEMM with explicit leading dims.
// mode 0: C=acc | 1: C+=acc | 2: C=relu(acc+aux[n])
// mode 5: mode 2 + pack hi/lo into P [gm, 2*Ksg]
#define BM 64
#define BN 64
#define BK 16
__global__ void sgemm(int M, int N, int K,
                      const float* __restrict__ A, int lda,
                      const float* __restrict__ B, int ldb,
                      float* C, int ldc, int transB, int mode,
                      const float* __restrict__ aux,
                      unsigned short* __restrict__ P, int Ksg) {
    __shared__ float As[BK][BM];
    __shared__ float Bs[BK][BN];
    int tid = threadIdx.x;
    int tx = tid & 15, ty = tid >> 4;
    int rowBase = blockIdx.y * BM;
    int colBase = blockIdx.x * BN;

    float acc[4][4];
#pragma unroll
    for (int i = 0; i < 4; i++)
#pragma unroll
        for (int j = 0; j < 4; j++) acc[i][j] = 0.f;

    for (int k0 = 0; k0 < K; k0 += BK) {
#pragma unroll
        for (int l = 0; l < 4; l++) {
            int idx = tid + l * 256;
            int m = idx >> 4, kk = idx & 15;
            int gm = rowBase + m, gk = k0 + kk;
            As[kk][m] = (gm < M && gk < K) ? A[(size_t)gm * lda + gk] : 0.f;
        }
        if (!transB) {
#pragma unroll
            for (int l = 0; l < 4; l++) {
                int idx = tid + l * 256;
                int kk = idx >> 6, n = idx & 63;
                int gn = colBase + n, gk = k0 + kk;
                Bs[kk][n] = (gk < K && gn < N) ? B[(size_t)gk * ldb + gn] : 0.f;
            }
        } else {
#pragma unroll
            for (int l = 0; l < 4; l++) {
                int idx = tid + l * 256;
                int n = idx >> 4, kk = idx & 15;
                int gn = colBase + n, gk = k0 + kk;
                Bs[kk][n] = (gk < K && gn < N) ? B[(size_t)gn * ldb + gk] : 0.f;
            }
        }
        __syncthreads();
#pragma unroll
        for (int k = 0; k < BK; k++) {
            float ra[4], rb[4];
#pragma unroll
            for (int i = 0; i < 4; i++) ra[i] = As[k][ty * 4 + i];
#pragma unroll
            for (int j = 0; j < 4; j++) rb[j] = Bs[k][tx * 4 + j];
#pragma unroll
            for (int i = 0; i < 4; i++)
#pragma unroll
                for (int j = 0; j < 4; j++) acc[i][j] += ra[i] * rb[j];
        }
        __syncthreads();
    }

#pragma unroll
    for (int i = 0; i < 4; i++) {
        int gm = rowBase + ty * 4 + i;
        if (gm >= M) continue;
#pragma unroll
        for (int j = 0; j < 4; j++) {
            int gn = colBase + tx * 4 + j;
            if (gn >= N) continue;
            size_t o = (size_t)gm * ldc + gn;
            float v = acc[i][j];
            if (mode == 0) {
                C[o] = v;
            } else if (mode == 1) {
                C[o] += v;
            } else if (mode == 2) {
                C[o] = fmaxf(v + aux[gn], 0.f);
            } else {  // mode 5
                float r = fmaxf(v + aux[gn], 0.f);
                C[o] = r;
                unsigned short h, l;
                split_bf16(r, h, l);
                size_t base = (size_t)gm * (2 * Ksg) + gn;
                P[base] = h;
                P[base + Ksg] = l;
            }
        }
    }
}

// ====== register-resident exact top-k selection (k=40, lower-index ties) ======
// Shared selection core: each thread holds 16 candidate scores in registers.
// kval = exp(score); dinv = 1/sqrt(sum kval).
__device__ __forceinline__ void topk_select_reg(float (&sc)[16], int row,
                                                int* __restrict__ kidx,
                                                float* __restrict__ kval,
                                                float* __restrict__ dinv) {
    __shared__ float wv[8];
    __shared__ int   wi[8];
    __shared__ int   bshare;
    int tid = threadIdx.x, lane = tid & 31, wid = tid >> 5;
    float rowsum = 0.f;
    for (int it = 0; it < KNN; it++) {
        float best = -3e38f; int bi = 1 << 30;
#pragma unroll
        for (int i = 0; i < 16; i++) {
            // ascending i => ascending global index for this thread: first win = lowest idx
            if (sc[i] > best) { best = sc[i]; bi = i * 256 + tid; }
        }
#pragma unroll
        for (int o = 16; o > 0; o >>= 1) {
            float ov = __shfl_down_sync(0xFFFFFFFFu, best, o);
            int   oi = __shfl_down_sync(0xFFFFFFFFu, bi, o);
            if (ov > best || (ov == best && oi < bi)) { best = ov; bi = oi; }
        }
        if (lane == 0) { wv[wid] = best; wi[wid] = bi; }
        __syncthreads();
        if (tid == 0) {
            float b = wv[0]; int xi = wi[0];
#pragma unroll
            for (int w = 1; w < 8; w++)
                if (wv[w] > b || (wv[w] == b && wi[w] < xi)) { b = wv[w]; xi = wi[w]; }
            bshare = xi;
            float ev = expf(b);
            kidx[row * KNN + it] = xi;
            kval[row * KNN + it] = ev;
            rowsum += ev;
        }
        __syncthreads();
        int w = bshare;
        if ((w & 255) == tid) {
            int ci = w >> 8;
#pragma unroll
            for (int i = 0; i < 16; i++)
                if (i == ci) sc[i] = -3e38f;
        }
    }
    if (tid == 0) dinv[row] = 1.f / sqrtf(rowsum);
}

// graph-1: fused adjacency (K=6 dot products on the fly) + top-k. No score matrix.
__global__ void knn1_fused(const float* __restrict__ x, const float* __restrict__ sq,
                           int* __restrict__ kidx, float* __restrict__ kval,
                           float* __restrict__ dinv) {
    int row = blockIdx.x, tid = threadIdx.x;
    __shared__ float xr[FIN];
    if (tid < FIN) xr[tid] = x[row * FIN + tid];
    __syncthreads();
    float sqr = sq[row];
    float sc[16];
#pragma unroll
    for (int i = 0; i < 16; i++) {
        int j = i * 256 + tid;
        const float* xj = x + (size_t)j * FIN;
        float dot = xr[0] * xj[0] + xr[1] * xj[1] + xr[2] * xj[2]
                  + xr[3] * xj[3] + xr[4] * xj[4] + xr[5] * xj[5];
        sc[i] = 2.f * dot - sqr - sq[j];
    }
    topk_select_reg(sc, row, kidx, kval, dinv);
}

// graph-2: top-k over a precomputed score row (loaded once into registers)
__global__ void topk_reg(const float* __restrict__ W,
                         int* __restrict__ kidx, float* __restrict__ kval,
                         float* __restrict__ dinv) {
    int row = blockIdx.x, tid = threadIdx.x;
    const float* wr = W + (size_t)row * NPTS;
    float sc[16];
#pragma unroll
    for (int i = 0; i < 16; i++) sc[i] = wr[i * 256 + tid];
    topk_select_reg(sc, row, kidx, kval, dinv);
}

// ================= sparse Laplacian apply (strided I/O) =================
// mode 0: Y = L X ; mode 1: Y = 2 L X - Prev
__global__ void spmm_lap(const float* __restrict__ X, int ldx,
                         const int* __restrict__ kidx,
                         const float* __restrict__ kval, const float* __restrict__ dinv,
                         float* __restrict__ Y, int ldy,
                         const float* __restrict__ Prev, int ldp,
                         int F, int mode) {
    int r = blockIdx.x;
    __shared__ int   sidx[KNN];
    __shared__ float sw[KNN];
    int tid = threadIdx.x;
    if (tid < KNN) {
        int c = kidx[r * KNN + tid];
        sidx[tid] = c;
        sw[tid] = kval[r * KNN + tid] * dinv[r] * dinv[c];
    }
    __syncthreads();
    for (int c = tid; c < F; c += blockDim.x) {
        float acc = X[(size_t)r * ldx + c];
#pragma unroll 8
        for (int j = 0; j < KNN; j++)
            acc -= sw[j] * X[(size_t)sidx[j] * ldx + c];
        if (mode) acc = 2.f * acc - Prev[(size_t)r * ldp + c];
        Y[(size_t)r * ldy + c] = acc;
    }
}

// sparse Laplacian + fused bf16 packing into pp2 slice (F = C1 fixed)
__global__ void spmm_pack(const float* __restrict__ X,
                          const int* __restrict__ kidx,
                          const float* __restrict__ kval, const float* __restrict__ dinv,
                          float* __restrict__ Y, const float* __restrict__ Prev,
                          int mode, unsigned short* __restrict__ P, int slice) {
    int r = blockIdx.x;
    __shared__ int   sidx[KNN];
    __shared__ float sw[KNN];
    int tid = threadIdx.x;
    if (tid < KNN) {
        int c = kidx[r * KNN + tid];
        sidx[tid] = c;
        sw[tid] = kval[r * KNN + tid] * dinv[r] * dinv[c];
    }
    __syncthreads();
    for (int c = tid; c < C1; c += blockDim.x) {
        float acc = X[(size_t)r * C1 + c];
#pragma unroll 8
        for (int j = 0; j < KNN; j++)
            acc -= sw[j] * X[(size_t)sidx[j] * C1 + c];
        if (mode) acc = 2.f * acc - Prev[(size_t)r * C1 + c];
        Y[(size_t)r * C1 + c] = acc;
        unsigned short h, l;
        split_bf16(acc, h, l);
        size_t base = (size_t)r * (2 * KSEG2) + slice * C1 + c;
        P[base] = h;
        P[base + KSEG2] = l;
    }
}

__global__ void build_xhat1(const float* __restrict__ x, const float* __restrict__ m1,
                            const float* __restrict__ t2, float* __restrict__ xh, int n) {
    int i = blockIdx.x * blockDim.x + threadIdx.x;
    if (i < n * 6) {
        int r = i / 6, f = i % 6;
        xh[r * 18 + f] = x[i];
        xh[r * 18 + 6 + f] = m1[i];
        xh[r * 18 + 12 + f] = 2.f * t2[i] - x[i];
    }
}

// Reeb Chebyshev fix on concatenated layout: rcat[r, 2000+c] = 2*rcat[r, 2000+c] - rcat[r, c]
__global__ void cheb_fix_reeb(float* __restrict__ rcat) {
    int i = blockIdx.x * blockDim.x + threadIdx.x;
    if (i < NRB * C1) {
        int r = i / C1, c = i % C1;
        rcat[r * KREEB + 2000 + c] = 2.f * rcat[r * KREEB + 2000 + c] - rcat[r * KREEB + c];
    }
}

__global__ void sccpool(const float* __restrict__ out, const int* __restrict__ sccs,
                        float* __restrict__ rcat) {
    int r = blockIdx.y;
    int c = blockIdx.x * 256 + threadIdx.x;
    if (c < C1) {
        float m = -3e38f;
        for (int s = 0; s < SCC_S; s++) {
            int n = sccs[r * SCC_S + s];
            m = fmaxf(m, out[(size_t)n * C1 + c]);
        }
        rcat[r * KREEB + c] = m;   // slice 0 = vfr
    }
}

__global__ void colmax(const float* __restrict__ M, float* __restrict__ outv,
                       int R, int Ncol, int off) {
    int c = blockIdx.x * 256 + threadIdx.x;
    if (c < Ncol) {
        float m = -3e38f;
        for (int r = 0; r < R; r++) m = fmaxf(m, M[(size_t)r * Ncol + c]);
        outv[off + c] = m;
    }
}

// two-stage column max over 4096 rows
__global__ void colmax_p1(const float* __restrict__ M, float* __restrict__ part, int Ncol) {
    int chunk = blockIdx.y;
    int c = blockIdx.x * 256 + threadIdx.x;
    if (c < Ncol) {
        float m = -3e38f;
        int r0 = chunk * 128;
        for (int r = r0; r < r0 + 128; r++) m = fmaxf(m, M[(size_t)r * Ncol + c]);
        part[(size_t)chunk * Ncol + c] = m;
    }
}
__global__ void colmax_p2(const float* __restrict__ part, float* __restrict__ outv,
                          int Ncol, int off) {
    int c = blockIdx.x * 256 + threadIdx.x;
    if (c < Ncol) {
        float m = -3e38f;
        for (int ch = 0; ch < 32; ch++) m = fmaxf(m, part[(size_t)ch * Ncol + c]);
        outv[off + c] = m;
    }
}

// two-stage regularizer: ss += || O^T @ Mv ||_F^2
__global__ void reg_p1(const float* __restrict__ O, const float* __restrict__ Mv,
                       float* __restrict__ part, int C) {
    int chunk = blockIdx.y;
    int c = blockIdx.x * 256 + threadIdx.x;
    __shared__ float sm[256 * 6];
    int n0 = chunk * 256;
    for (int i = threadIdx.x; i < 256 * 6; i += 256) sm[i] = Mv[n0 * 6 + i];
    __syncthreads();
    if (c < C) {
        float acc[6] = {0, 0, 0, 0, 0, 0};
        for (int t = 0; t < 256; t++) {
            float v = O[(size_t)(n0 + t) * C + c];
#pragma unroll
            for (int f = 0; f < 6; f++) acc[f] += v * sm[t * 6 + f];
        }
#pragma unroll
        for (int f = 0; f < 6; f++) part[((size_t)chunk * C + c) * 6 + f] = acc[f];
    }
}
__global__ void reg_p2(const float* __restrict__ part, float* ss, int C) {
    int c = blockIdx.x * 256 + threadIdx.x;
    if (c < C) {
        float s = 0.f;
#pragma unroll
        for (int f = 0; f < 6; f++) {
            float a = 0.f;
            for (int ch = 0; ch < 16; ch++) a += part[((size_t)ch * C + c) * 6 + f];
            s += a * a;
        }
        atomicAdd(ss, s);
    }
}

__global__ void fc_kernel(const float* __restrict__ in, const float* __restrict__ Wf,
                          const float* __restrict__ bf, float* __restrict__ outv,
                          int In, int Out, int doRelu) {
    __shared__ float sIn[2048];
    for (int i = threadIdx.x; i < In; i += blockDim.x) sIn[i] = in[i];
    __syncthreads();
    int o = threadIdx.x;
    if (o < Out) {
        float a = bf[o];
        for (int i = 0; i < In; i++) a += sIn[i] * Wf[(size_t)i * Out + o];
        outv[o] = doRelu ? fmaxf(a, 0.f) : a;
    }
}

__global__ void finalize2(const float* __restrict__ ss,
                          const float* __restrict__ fc1w, const float* __restrict__ fc1b,
                          const float* __restrict__ fc2w, const float* __restrict__ fc2b,
                          const float* __restrict__ fc3w, const float* __restrict__ fc3b,
                          float* out) {
    __shared__ float red[256];
    int tid = threadIdx.x;
    float s1, s2, s3;
    float a = 0.f;
    for (int i = tid; i < 2000; i += 256) { float v = fc1w[(size_t)i * 512]; a += v * v; }
    red[tid] = a; __syncthreads();
    for (int s = 128; s > 0; s >>= 1) { if (tid < s) red[tid] += red[tid + s]; __syncthreads(); }
    s1 = red[0]; __syncthreads();
    a = 0.f;
    for (int i = tid; i < 512; i += 256) { float v = fc2w[(size_t)i * 128]; a += v * v; }
    red[tid] = a; __syncthreads();
    for (int s = 128; s > 0; s >>= 1) { if (tid < s) red[tid] += red[tid + s]; __syncthreads(); }
    s2 = red[0]; __syncthreads();
    a = 0.f;
    for (int i = tid; i < 128; i += 256) { float v = fc3w[(size_t)i * 40]; a += v * v; }
    red[tid] = a; __syncthreads();
    for (int s = 128; s > 0; s >>= 1) { if (tid < s) red[tid] += red[tid + s]; __syncthreads(); }
    s3 = red[0];
    if (tid == 0) {
        out[40] = sqrtf(ss[0]);
        out[41] = sqrtf(ss[1]);
        out[42] = s1;
        out[43] = fc1b[0] * fc1b[0];
        out[44] = s2;
        out[45] = fc2b[0] * fc2b[0];
        out[46] = s3;
        out[47] = fc3b[0] * fc3b[0];
    }
}

static inline dim3 gemmGrid(int M, int N) {
    return dim3((N + BN - 1) / BN, (M + BM - 1) / BM);
}

extern "C" void kernel_launch(void* const* d_in, const int* in_sizes, int n_in,
                              void* d_out, int out_size) {
    const float* x     = (const float*)d_in[0];
    const float* Lr    = (const float*)d_in[5];
    const int*   sccs  = (const int*)d_in[6];
    const float* W1    = (const float*)d_in[7];
    const float* b1    = (const float*)d_in[8];
    const float* W2    = (const float*)d_in[9];
    const float* b2    = (const float*)d_in[10];
    const float* Wr    = (const float*)d_in[11];
    const float* br    = (const float*)d_in[12];
    const float* fc1w  = (const float*)d_in[13];
    const float* fc1b  = (const float*)d_in[14];
    const float* fc2w  = (const float*)d_in[15];
    const float* fc2b  = (const float*)d_in[16];
    const float* fc3w  = (const float*)d_in[17];
    const float* fc3b  = (const float*)d_in[18];
    float* out = (float*)d_out;

    float *pA, *pout, *pout2, *pTxA, *pTxB, *pxh, *pM1, *pM2, *pT2v;
    float *psq, *psq2, *pdinv, *pkval, *prcat, *poutr, *pfeat, *ph1, *ph2, *pss;
    float *pcm, *prg;
    int *pkidx;
    unsigned short *pp1, *pp2, *ppb;
    cudaGetSymbolAddress((void**)&pA, g_A);
    cudaGetSymbolAddress((void**)&pout, g_out);
    cudaGetSymbolAddress((void**)&pout2, g_out2);
    cudaGetSymbolAddress((void**)&pTxA, g_TxA);
    cudaGetSymbolAddress((void**)&pTxB, g_TxB);
    cudaGetSymbolAddress((void**)&pxh, g_xhat1);
    cudaGetSymbolAddress((void**)&pM1, g_M1);
    cudaGetSymbolAddress((void**)&pM2, g_M2);
    cudaGetSymbolAddress((void**)&pT2v, g_T2v);
    cudaGetSymbolAddress((void**)&psq, g_sq);
    cudaGetSymbolAddress((void**)&psq2, g_sq2);
    cudaGetSymbolAddress((void**)&pdinv, g_dinv);
    cudaGetSymbolAddress((void**)&pkidx, g_kidx);
    cudaGetSymbolAddress((void**)&pkval, g_kval);
    cudaGetSymbolAddress((void**)&prcat, g_rcat);
    cudaGetSymbolAddress((void**)&poutr, g_outr);
    cudaGetSymbolAddress((void**)&pfeat, g_feat);
    cudaGetSymbolAddress((void**)&ph1, g_h1);
    cudaGetSymbolAddress((void**)&ph2, g_h2);
    cudaGetSymbolAddress((void**)&pss, g_ss);
    cudaGetSymbolAddress((void**)&pcm, g_cmpart);
    cudaGetSymbolAddress((void**)&prg, g_regpart);
    cudaGetSymbolAddress((void**)&pp1, g_packA1);
    cudaGetSymbolAddress((void**)&pp2, g_packA2);
    cudaGetSymbolAddress((void**)&ppb, g_packB2);

    cudaMemsetAsync(pss, 0, 2 * sizeof(float), 0);

    // ===== graph 1 (K=6): fused adjacency + top-k, no score matrix =====
    rowsq_kernel<<<NPTS, 256>>>(x, psq, NPTS, FIN);
    knn1_fused<<<NPTS, 256>>>(x, psq, pkidx, pkval, pdinv);

    spmm_lap<<<NPTS, 64>>>(x, FIN, pkidx, pkval, pdinv, pM1, FIN, nullptr, 0, FIN, 0);
    spmm_lap<<<NPTS, 64>>>(pM1, FIN, pkidx, pkval, pdinv, pT2v, FIN, nullptr, 0, FIN, 0);
    build_xhat1<<<(NPTS * 6 + 255) / 256, 256>>>(x, pM1, pT2v, pxh, NPTS);
    // conv1 with fused hi/lo pack into adjacency operand pp1
    sgemm<<<gemmGrid(NPTS, C1), 256>>>(NPTS, C1, 18, pxh, 18, W1, C1, pout, C1,
                                       0, 5, b1, pp1, KSEG1);
    pad_pack<<<384, 256>>>(pp1, C1, KSEG1, NPTS);

    reg_p1<<<dim3(4, 16), 256>>>(pout, pM1, prg, C1);
    reg_p2<<<4, 256>>>(prg, pss + 0, C1);
    sccpool<<<dim3((C1 + 255) / 256, NRB), 256>>>(pout, sccs, prcat);

    // W2^T pack (covers all padding itself)
    pack_split_T<<<dim3((KSEG2 + 31) / 32, NPAD2 / 32), dim3(32, 8)>>>(W2, KCAT, C2, ppb, KSEG2, NPAD2);

    // ===== graph 2: adjacency via symmetric tensor-core GEMM (round-13 config) =====
    rowsq_kernel<<<NPTS, 256>>>(pout, psq2, NPTS, C1);
    gemm_mma<4, 1><<<dim3(32, 32), 256>>>(pp1, 2 * KSEG1, pp1, 2 * KSEG1,
                                          KSEG1, NPTS, pA, NPTS, psq2);
    topk_reg<<<NPTS, 256>>>(pA, pkidx, pkval, pdinv);
    spmm_lap<<<NPTS, 64>>>(x, FIN, pkidx, pkval, pdinv, pM2, FIN, nullptr, 0, FIN, 0);

    // Chebyshev basis T0..T5 packed directly into pp2 (fp32 recursion in TxA/TxB)
    pack_slice<<<(NPTS * C1 + 255) / 256, 256>>>(pout, pp2, 0);                        // T0
    pad_pack<<<256, 256>>>(pp2, KCAT, KSEG2, NPTS);
    spmm_pack<<<NPTS, 256>>>(pout, pkidx, pkval, pdinv, pTxA, nullptr, 0, pp2, 1);     // T1
    spmm_pack<<<NPTS, 256>>>(pTxA, pkidx, pkval, pdinv, pTxB, pout, 1, pp2, 2);        // T2
    spmm_pack<<<NPTS, 256>>>(pTxB, pkidx, pkval, pdinv, pTxA, pTxA, 1, pp2, 3);        // T3
    spmm_pack<<<NPTS, 256>>>(pTxA, pkidx, pkval, pdinv, pTxB, pTxB, 1, pp2, 4);        // T4
    spmm_pack<<<NPTS, 256>>>(pTxB, pkidx, pkval, pdinv, pTxA, pTxA, 1, pp2, 5);        // T5

    // conv2 via tensor cores: out2 = relu(xhat2 @ W2 + b2), K=6016 padded
    gemm_mma<2, 0><<<dim3(NPAD2 / 128, 32), 256>>>(pp2, 2 * KSEG2, ppb, 2 * KSEG2,
                                                   KSEG2, C2, pout2, C2, b2);

    reg_p1<<<dim3(4, 16), 256>>>(pout2, pM2, prg, C2);
    reg_p2<<<4, 256>>>(prg, pss + 1, C2);
    colmax_p1<<<dim3(4, 32), 256>>>(pout2, pcm, C2);
    colmax_p2<<<4, 256>>>(pcm, pfeat, C2, C2);

    // ===== Reeb branch: concatenated basis [vfr|Tr1|Tr2] then one K=3000 GEMM =====
    sgemm<<<gemmGrid(NRB, C1), 256>>>(NRB, C1, NRB, Lr, NRB, prcat, KREEB, prcat + 1000, KREEB,
                                      0, 0, nullptr, nullptr, 0);
    sgemm<<<gemmGrid(NRB, C1), 256>>>(NRB, C1, NRB, Lr, NRB, prcat + 1000, KREEB, prcat + 2000, KREEB,
                                      0, 0, nullptr, nullptr, 0);
    cheb_fix_reeb<<<(NRB * C1 + 255) / 256, 256>>>(prcat);
    sgemm<<<gemmGrid(NRB, C2), 256>>>(NRB, C2, KREEB, prcat, KREEB, Wr, C2, poutr, C2,
                                      0, 2, br, nullptr, 0);
    colmax<<<(C2 + 255) / 256, 256>>>(poutr, pfeat, NRB, C2, 0);

    // ===== FC head =====
    fc_kernel<<<1, 512>>>(pfeat, fc1w, fc1b, ph1, 2 * C2, 512, 1);
    fc_kernel<<<1, 128>>>(ph1, fc2w, fc2b, ph2, 512, 128, 1);
    fc_kernel<<<1, 64>>>(ph2, fc3w, fc3b, out, 128, NCLS, 0);

    finalize2<<<1, 256>>>(pss, fc1w, fc1b, fc2w, fc2b, fc3w, fc3b, out);

    (void)in_sizes; (void)n_in; (void)out_size;
}